// round 16
// baseline (speedup 1.0000x reference)
#include <cuda_runtime.h>
#include <stdint.h>
#include <math.h>

#define BSZ    8
#define SEQ    1024
#define DMODEL 1024
#define NHEAD  16
#define HDIM   64
#define MROWS  (BSZ*SEQ)       // 8192
#define NHB    (BSZ*NHEAD)     // 128

#define FMIN_VAL (-3.402823466e38f)

// ---------------------------------------------------------------------------
// Scratch (device globals). k-PERMUTED planes: each 8-float k-group stored
// [k0,k4,k1,k5,k2,k6,k3,k7] so tf32 fragment pairs (k,k+4) load as one LDS.64.
// ---------------------------------------------------------------------------
__device__ float g_Q[MROWS*DMODEL];        // tf32-valued, hd-permuted
__device__ float g_K[MROWS*DMODEL];        // tf32-valued, hd-permuted
__device__ float g_V[MROWS*DMODEL];        // tf32-valued, natural
__device__ float g_A32[MROWS*DMODEL];      // act plane (q) / attn-O, k-permuted
__device__ float g_B32[MROWS*DMODEL];      // act plane (k)
__device__ float g_C32[MROWS*DMODEL];      // act plane (v)
__device__ float g_W32[4*DMODEL*DMODEL];   // weight planes, k-permuted
__device__ float g_Vsum[NHB*HDIM];         // per-head V column sums

// ---------------------------------------------------------------------------
// PTX helpers
// ---------------------------------------------------------------------------
#define MMA_TF32(d, a0,a1,a2,a3, b0,b1) \
  asm volatile("mma.sync.aligned.m16n8k8.row.col.f32.tf32.tf32.f32 " \
   "{%0,%1,%2,%3}, {%4,%5,%6,%7}, {%8,%9}, {%0,%1,%2,%3};" \
   : "+f"((d)[0]),"+f"((d)[1]),"+f"((d)[2]),"+f"((d)[3]) \
   : "r"(a0),"r"(a1),"r"(a2),"r"(a3),"r"(b0),"r"(b1))

__device__ __forceinline__ uint32_t rna(float x){
    uint32_t r; asm("cvt.rna.tf32.f32 %0, %1;" : "=r"(r) : "f"(x)); return r;
}
__device__ __forceinline__ uint32_t smem_u32(const void* p){
    uint32_t a;
    asm("{ .reg .u64 t; cvta.to.shared.u64 t, %1; cvt.u32.u64 %0, t; }"
        : "=r"(a) : "l"(p));
    return a;
}
#define CP16(dst,src) asm volatile("cp.async.cg.shared.global [%0], [%1], 16;"::"r"(dst),"l"(src))
#define CP_COMMIT()   asm volatile("cp.async.commit_group;":::"memory")
#define CP_WAIT0()    asm volatile("cp.async.wait_group 0;":::"memory")
#define CP_WAIT1()    asm volatile("cp.async.wait_group 1;":::"memory")

// ---------------------------------------------------------------------------
// fp32 -> tf32-rounded, k-group interleaved. One thread per 8-float group.
// ---------------------------------------------------------------------------
__device__ __forceinline__ void conv_group(const float* X, float* Y, int i){
    float4 lo = ((const float4*)X)[2*i];
    float4 hi = ((const float4*)X)[2*i+1];
    uint4 o0, o1;
    o0.x = rna(lo.x); o0.y = rna(hi.x); o0.z = rna(lo.y); o0.w = rna(hi.y);
    o1.x = rna(lo.z); o1.y = rna(hi.z); o1.z = rna(lo.w); o1.w = rna(hi.w);
    ((uint4*)Y)[2*i]   = o0;
    ((uint4*)Y)[2*i+1] = o1;
}

__global__ void __launch_bounds__(256) conv_w4(
    const float* __restrict__ w0, const float* __restrict__ w1,
    const float* __restrict__ w2, const float* __restrict__ w3,
    float* __restrict__ W32, int n8)
{
    int i = blockIdx.x*256 + threadIdx.x;
    if (i >= n8) return;
    const float* src = (blockIdx.y==0) ? w0 : (blockIdx.y==1) ? w1 :
                       (blockIdx.y==2) ? w2 : w3;
    conv_group(src, W32 + (size_t)blockIdx.y*DMODEL*DMODEL, i);
}

__global__ void __launch_bounds__(256) conv_a3(
    const float* __restrict__ x0, const float* __restrict__ x1,
    const float* __restrict__ x2,
    float* __restrict__ y0, float* __restrict__ y1, float* __restrict__ y2,
    int n8)
{
    int i = blockIdx.x*256 + threadIdx.x;
    if (i >= n8) return;
    const float* src = (blockIdx.y==0) ? x0 : (blockIdx.y==1) ? x1 : x2;
    float*       dst = (blockIdx.y==0) ? y0 : (blockIdx.y==1) ? y1 : y2;
    conv_group(src, dst, i);
}

// ---------------------------------------------------------------------------
// Per-head V column sums — 512 threads/CTA, 4 partial accumulators
// ---------------------------------------------------------------------------
__global__ void __launch_bounds__(512) vsum_kernel(
    const float* __restrict__ V, float* __restrict__ Vs)
{
    __shared__ float red[8][64];
    const float* Vh = V + (size_t)blockIdx.x*65536;
    const int c = threadIdx.x & 63;
    const int g = threadIdx.x >> 6;
    const float* p = Vh + (size_t)(g*128)*HDIM + c;
    float s0=0.f, s1=0.f, s2=0.f, s3=0.f;
    #pragma unroll 8
    for (int r = 0; r < 128; r += 4) {
        s0 += p[(r+0)*HDIM];
        s1 += p[(r+1)*HDIM];
        s2 += p[(r+2)*HDIM];
        s3 += p[(r+3)*HDIM];
    }
    red[g][c] = (s0+s1) + (s2+s3);
    __syncthreads();
    if (g == 0) {
        float t = 0.f;
        #pragma unroll
        for (int k = 0; k < 8; k++) t += red[k][c];
        Vs[blockIdx.x*HDIM + c] = t;
    }
}

// ---------------------------------------------------------------------------
// GEMM core: 128x128 tile, 2 CTA/SM, single-stream tf32, LDS.64 fragments,
// THREE-STAGE cp.async pipeline (2 chunks in flight, wait_group 1).
// mode: 0 = plain fp32 out, 1 = rna out (natural), 2 = rna + k-permuted out
// ---------------------------------------------------------------------------
#define GSTR 36
#define GBUF (2*128*GSTR)             // floats per stage (A+B)
#define GEMM_SMEM (3*GBUF*4)          // 110592 B; 2 CTAs = 221184 <= 228K

__device__ __forceinline__ void gemm_body(
    const float* __restrict__ A, const float* __restrict__ W,
    const float* __restrict__ bias, float* __restrict__ C,
    float alpha, int mode, float* gsm, uint32_t sbase)
{
    const int tid  = threadIdx.x;
    const int lane = tid & 31;
    const int wid  = tid >> 5;
    const int wm   = (wid & 1) * 64;
    const int wn   = (wid >> 1) * 32;
    const int bm   = blockIdx.y * 128;
    const int bn   = blockIdx.x * 128;

    float acc[4][4][4];
    #pragma unroll
    for (int a=0;a<4;a++)
        #pragma unroll
        for (int b=0;b<4;b++)
            #pragma unroll
            for (int r=0;r<4;r++) acc[a][b][r]=0.f;

    const int lrow = tid >> 3;
    const int lseg = (tid & 7) * 4;

    #define ISSUE_CHUNK(k0, buf)                                               \
    do {                                                                       \
        uint32_t ab = sbase + (buf)*GBUF*4;                                    \
        uint32_t bb = ab + 128*GSTR*4;                                         \
        _Pragma("unroll")                                                      \
        for (int it = 0; it < 4; it++) {                                       \
            int row = it*32 + lrow;                                            \
            CP16(ab + (row*GSTR + lseg)*4,                                     \
                 &A[(size_t)(bm+row)*DMODEL + (k0) + lseg]);                   \
            CP16(bb + (row*GSTR + lseg)*4,                                     \
                 &W[(size_t)(bn+row)*DMODEL + (k0) + lseg]);                   \
        }                                                                      \
        CP_COMMIT();                                                           \
    } while(0)

    ISSUE_CHUNK(0, 0);
    ISSUE_CHUNK(32, 1);

    const int q2 = (lane & 3) * 2;
    int buf = 0;
    for (int c = 0; c < 32; c++) {
        if (c == 31) CP_WAIT0(); else CP_WAIT1();   // chunk c resident
        __syncthreads();   // also orders compute(c-1) before issue into buf(c+2)
        if (c < 30) ISSUE_CHUNK((c+2)*32, (buf+2)%3);

        const float* As_ = gsm + buf*GBUF;
        const float* Bs_ = As_ + 128*GSTR;

        #pragma unroll
        for (int ks = 0; ks < 4; ks++) {
            const int kb = ks*8 + q2;
            float2 bfr[4];
            #pragma unroll
            for (int nt = 0; nt < 4; nt++)
                bfr[nt] = *(const float2*)(Bs_ + (wn + nt*8 + (lane>>2))*GSTR + kb);
            #pragma unroll
            for (int mt = 0; mt < 4; mt++) {
                const float* ap = As_ + (wm + mt*16 + (lane>>2))*GSTR + kb;
                float2 aA = *(const float2*)ap;
                float2 aB = *(const float2*)(ap + 8*GSTR);
                uint32_t a0 = __float_as_uint(aA.x);
                uint32_t a2 = __float_as_uint(aA.y);
                uint32_t a1 = __float_as_uint(aB.x);
                uint32_t a3 = __float_as_uint(aB.y);
                #pragma unroll
                for (int nt = 0; nt < 4; nt++)
                    MMA_TF32(acc[mt][nt], a0,a1,a2,a3,
                             __float_as_uint(bfr[nt].x), __float_as_uint(bfr[nt].y));
            }
        }
        buf = (buf == 2) ? 0 : buf + 1;
    }
    #undef ISSUE_CHUNK
    __syncthreads();

    const int q = lane & 3;
    const int pa = (q < 2) ? 4*q     : 4*q - 7;
    const int pb = (q < 2) ? 4*q + 2 : 4*q - 5;
    #pragma unroll
    for (int mt = 0; mt < 4; mt++) {
        const int row = bm + wm + mt*16 + (lane >> 2);
        #pragma unroll
        for (int nt = 0; nt < 4; nt++) {
            const int gb  = bn + wn + nt*8;
            const int col = gb + 2*q;
            const float bx = bias[col], by = bias[col+1];
            float2 v0, v1;
            v0.x = alpha*(acc[mt][nt][0] + bx);
            v0.y = alpha*(acc[mt][nt][1] + by);
            v1.x = alpha*(acc[mt][nt][2] + bx);
            v1.y = alpha*(acc[mt][nt][3] + by);
            if (mode) {
                v0.x = __uint_as_float(rna(v0.x)); v0.y = __uint_as_float(rna(v0.y));
                v1.x = __uint_as_float(rna(v1.x)); v1.y = __uint_as_float(rna(v1.y));
            }
            if (mode == 2) {
                C[(size_t)row*DMODEL + gb + pa]     = v0.x;
                C[(size_t)row*DMODEL + gb + pb]     = v0.y;
                C[(size_t)(row+8)*DMODEL + gb + pa] = v1.x;
                C[(size_t)(row+8)*DMODEL + gb + pb] = v1.y;
            } else {
                *(float2*)&C[(size_t)row*DMODEL + col]     = v0;
                *(float2*)&C[(size_t)(row+8)*DMODEL + col] = v1;
            }
        }
    }
}

__global__ void __launch_bounds__(256,2) gemm_qkv(
    const float* __restrict__ Aq, const float* __restrict__ Ak,
    const float* __restrict__ Av, const float* __restrict__ W32,
    const float* __restrict__ bq, const float* __restrict__ bk,
    const float* __restrict__ bv,
    float* __restrict__ Q, float* __restrict__ K, float* __restrict__ V)
{
    extern __shared__ float gsm[];
    const uint32_t sbase = smem_u32(gsm);
    const int z = blockIdx.z;
    const float* A  = (z==0) ? Aq : (z==1) ? Ak : Av;
    const float* Wz = W32 + (size_t)z*DMODEL*DMODEL;
    const float* bs = (z==0) ? bq : (z==1) ? bk : bv;
    float*       C  = (z==0) ? Q  : (z==1) ? K  : V;
    const float alpha = (z==0) ? 0.25f : 1.0f;
    const int   mode  = (z==2) ? 1 : 2;
    gemm_body(A, Wz, bs, C, alpha, mode, gsm, sbase);
}

__global__ void __launch_bounds__(256,2) gemm_single(
    const float* __restrict__ A, const float* __restrict__ W,
    const float* __restrict__ bias, float* __restrict__ C,
    float alpha, int mode)
{
    extern __shared__ float gsm[];
    gemm_body(A, W, bias, C, alpha, mode, gsm, smem_u32(gsm));
}

// ---------------------------------------------------------------------------
// Flash attention (exact R12 champion): tf32 HMMA, tile skipping, no online
// max, fused KV prefetch at loop bottom.
// ---------------------------------------------------------------------------
#define ASTR 72
#define A_QS 0
#define A_KS (128*ASTR)
#define A_VS (A_KS + 64*ASTR)
#define A_PS (A_VS + 64*ASTR)
#define ATTN_SMEM ((A_PS + 128*ASTR)*4)   // 110592 B

__global__ void __launch_bounds__(256,2) attn_kernel(
    const float* __restrict__ Qg, const float* __restrict__ Kg,
    const float* __restrict__ Vg, const float* __restrict__ Vsum,
    float* __restrict__ O32)
{
    extern __shared__ float smf[];
    const uint32_t sbase = smem_u32(smf);

    const int hb = blockIdx.y;
    const int q0 = blockIdx.x * 128;
    const float* Qh = Qg + (size_t)hb*65536;
    const float* Kh = Kg + (size_t)hb*65536;
    const float* Vh = Vg + (size_t)hb*65536;

    const int tid  = threadIdx.x;
    const int lane = tid & 31;
    const int wid  = tid >> 5;
    const int qr   = (lane >> 2);
    const int qc   = (lane & 3);
    const int q2   = qc * 2;

    const int lrow = tid >> 4;
    const int lseg = (tid & 15) * 4;

    #define ISSUE_KV(kv0)                                                      \
    do {                                                                       \
        _Pragma("unroll")                                                      \
        for (int it = 0; it < 4; it++) {                                       \
            int row = it*16 + lrow;                                            \
            CP16(sbase + (A_KS + row*ASTR + lseg)*4,                           \
                 &Kh[(size_t)((kv0)+row)*HDIM + lseg]);                        \
            CP16(sbase + (A_VS + row*ASTR + lseg)*4,                           \
                 &Vh[(size_t)((kv0)+row)*HDIM + lseg]);                        \
        }                                                                      \
        CP_COMMIT();                                                           \
    } while(0)

    const int t0 = 2*blockIdx.x;

    #pragma unroll
    for (int it = 0; it < 8; it++) {
        int row = it*16 + lrow;
        CP16(sbase + (A_QS + row*ASTR + lseg)*4,
             &Qh[(size_t)(q0+row)*HDIM + lseg]);
    }
    ISSUE_KV(t0*64);

    float oa[8][4];
    #pragma unroll
    for (int nt=0;nt<8;nt++)
        #pragma unroll
        for (int r=0;r<4;r++) oa[nt][r]=0.f;
    float l0 = 0.f, l1 = 0.f;

    const int rloc = wid*16 + qr;
    const int rg0  = q0 + rloc;
    const int rg1  = rg0 + 8;
    const float* Qs = smf + A_QS;
    const float* Ks = smf + A_KS;
    const float* Vs = smf + A_VS;
    float*       Ps = smf + A_PS;

    const int pa = (qc < 2) ? 4*qc     : 4*qc - 7;
    const int pb = (qc < 2) ? 4*qc + 2 : 4*qc - 5;

    for (int t = t0; t < 16; t++) {
        const int kv0 = t*64;
        CP_WAIT0();
        __syncthreads();

        float sa[8][4];
        #pragma unroll
        for (int nt=0;nt<8;nt++)
            #pragma unroll
            for (int r=0;r<4;r++) sa[nt][r]=0.f;

        #pragma unroll
        for (int ks = 0; ks < 8; ks++) {
            const int kb = ks*8 + q2;
            float2 qA = *(const float2*)(Qs + rloc*ASTR + kb);
            float2 qB = *(const float2*)(Qs + (rloc+8)*ASTR + kb);
            uint32_t a0 = __float_as_uint(qA.x);
            uint32_t a2 = __float_as_uint(qA.y);
            uint32_t a1 = __float_as_uint(qB.x);
            uint32_t a3 = __float_as_uint(qB.y);
            #pragma unroll
            for (int nt = 0; nt < 8; nt++) {
                float2 kf = *(const float2*)(Ks + (qr + nt*8)*ASTR + kb);
                MMA_TF32(sa[nt], a0,a1,a2,a3,
                         __float_as_uint(kf.x), __float_as_uint(kf.y));
            }
        }

        float ts0 = 0.f, ts1 = 0.f;
        #pragma unroll
        for (int nt = 0; nt < 8; nt++) {
            const int cg = kv0 + nt*8 + q2;
            if (cg   <= rg0) sa[nt][0] = FMIN_VAL;
            if (cg+1 <= rg0) sa[nt][1] = FMIN_VAL;
            if (cg   <= rg1) sa[nt][2] = FMIN_VAL;
            if (cg+1 <= rg1) sa[nt][3] = FMIN_VAL;
            sa[nt][0] = __expf(sa[nt][0]);
            sa[nt][1] = __expf(sa[nt][1]);
            sa[nt][2] = __expf(sa[nt][2]);
            sa[nt][3] = __expf(sa[nt][3]);
            ts0 += sa[nt][0] + sa[nt][1];
            ts1 += sa[nt][2] + sa[nt][3];
        }
        ts0 += __shfl_xor_sync(0xffffffffu, ts0, 1);
        ts0 += __shfl_xor_sync(0xffffffffu, ts0, 2);
        ts1 += __shfl_xor_sync(0xffffffffu, ts1, 1);
        ts1 += __shfl_xor_sync(0xffffffffu, ts1, 2);
        l0 += ts0;
        l1 += ts1;

        #pragma unroll
        for (int nt = 0; nt < 8; nt++) {
            float* pr0 = Ps + rloc*ASTR + nt*8;
            float* pr1 = Ps + (rloc+8)*ASTR + nt*8;
            pr0[pa] = __uint_as_float(rna(sa[nt][0]));
            pr0[pb] = __uint_as_float(rna(sa[nt][1]));
            pr1[pa] = __uint_as_float(rna(sa[nt][2]));
            pr1[pb] = __uint_as_float(rna(sa[nt][3]));
        }
        __syncwarp();

        #pragma unroll
        for (int ks = 0; ks < 8; ks++) {
            const int kb = ks*8 + q2;
            float2 pA = *(const float2*)(Ps + rloc*ASTR + kb);
            float2 pB = *(const float2*)(Ps + (rloc+8)*ASTR + kb);
            uint32_t a0 = __float_as_uint(pA.x);
            uint32_t a2 = __float_as_uint(pA.y);
            uint32_t a1 = __float_as_uint(pB.x);
            uint32_t a3 = __float_as_uint(pB.y);
            const float* vb = Vs + (ks*8 + qc)*ASTR + qr;
            #pragma unroll
            for (int nt = 0; nt < 8; nt++) {
                uint32_t b0 = __float_as_uint(vb[nt*8]);
                uint32_t b1 = __float_as_uint(vb[4*ASTR + nt*8]);
                MMA_TF32(oa[nt], a0,a1,a2,a3, b0,b1);
            }
        }
        __syncthreads();
        if (t < 15) ISSUE_KV(kv0+64);
    }
    #undef ISSUE_KV

    if (rg1 == SEQ-1) {
        l1 = (float)SEQ;
        #pragma unroll
        for (int nt = 0; nt < 8; nt++) {
            const int col = nt*8 + q2;
            oa[nt][2] = Vsum[hb*HDIM + col];
            oa[nt][3] = Vsum[hb*HDIM + col + 1];
        }
    }

    const float i0 = 1.f / l0, i1 = 1.f / l1;
    const size_t slab = (size_t)hb * 65536;
    #pragma unroll
    for (int nt = 0; nt < 8; nt++) {
        float* o0 = O32 + slab + (size_t)rg0*HDIM + nt*8;
        float* o1 = O32 + slab + (size_t)rg1*HDIM + nt*8;
        o0[pa] = __uint_as_float(rna(oa[nt][0]*i0));
        o0[pb] = __uint_as_float(rna(oa[nt][1]*i0));
        o1[pa] = __uint_as_float(rna(oa[nt][2]*i1));
        o1[pb] = __uint_as_float(rna(oa[nt][3]*i1));
    }
}

// ---------------------------------------------------------------------------
// Launch
// ---------------------------------------------------------------------------
extern "C" void kernel_launch(void* const* d_in, const int* in_sizes, int n_in,
                              void* d_out, int out_size) {
    const float* q_in = (const float*)d_in[0];
    const float* k_in = (const float*)d_in[1];
    const float* v_in = (const float*)d_in[2];
    const float* wq   = (const float*)d_in[3];
    const float* bq   = (const float*)d_in[4];
    const float* wk   = (const float*)d_in[5];
    const float* bk   = (const float*)d_in[6];
    const float* wv   = (const float*)d_in[7];
    const float* bv   = (const float*)d_in[8];
    const float* wo   = (const float*)d_in[9];
    const float* bo   = (const float*)d_in[10];
    float* out = (float*)d_out;

    float *Qp, *Kp, *Vp, *Vs, *A32, *B32, *C32, *W32;
    cudaGetSymbolAddress((void**)&Qp,  g_Q);
    cudaGetSymbolAddress((void**)&Kp,  g_K);
    cudaGetSymbolAddress((void**)&Vp,  g_V);
    cudaGetSymbolAddress((void**)&Vs,  g_Vsum);
    cudaGetSymbolAddress((void**)&A32, g_A32);
    cudaGetSymbolAddress((void**)&B32, g_B32);
    cudaGetSymbolAddress((void**)&C32, g_C32);
    cudaGetSymbolAddress((void**)&W32, g_W32);

    cudaFuncSetAttribute(gemm_qkv,    cudaFuncAttributeMaxDynamicSharedMemorySize, GEMM_SMEM);
    cudaFuncSetAttribute(gemm_single, cudaFuncAttributeMaxDynamicSharedMemorySize, GEMM_SMEM);
    cudaFuncSetAttribute(attn_kernel, cudaFuncAttributeMaxDynamicSharedMemorySize, ATTN_SMEM);

    const int WP = DMODEL*DMODEL;
    dim3 blk(256);
    const int NA8 = MROWS*DMODEL/8;
    const int NW8 = DMODEL*DMODEL/8;

    // tf32 plane conversions
    conv_w4<<<dim3(NW8/256, 4), blk>>>(wq, wk, wv, wo, W32, NW8);
    conv_a3<<<dim3(NA8/256, 3), blk>>>(q_in, k_in, v_in, A32, B32, C32, NA8);

    // Fused Q/K/V projections (128x128 tiles, wave-packed, 3-stage pipeline)
    dim3 gqkv(DMODEL/128, MROWS/128, 3);  // (8, 64, 3)
    gemm_qkv<<<gqkv, blk, GEMM_SMEM>>>(A32, B32, C32, W32, bq, bk, bv, Qp, Kp, Vp);

    // Per-head V column sums
    vsum_kernel<<<NHB, 512>>>(Vp, Vs);

    // Attention (tile skipping, no online max)
    dim3 gattn(SEQ/128, NHB);            // (8, 128)
    attn_kernel<<<gattn, blk, ATTN_SMEM>>>(Qp, Kp, Vp, Vs, A32);

    // Output projection
    dim3 gproj(DMODEL/128, MROWS/128);   // (8, 64)
    gemm_single<<<gproj, blk, GEMM_SMEM>>>(A32, W32+3*WP, bo, out, 1.0f, 0);
}

// round 17
// speedup vs baseline: 1.2023x; 1.2023x over previous
#include <cuda_runtime.h>
#include <stdint.h>
#include <math.h>

#define BSZ    8
#define SEQ    1024
#define DMODEL 1024
#define NHEAD  16
#define HDIM   64
#define MROWS  (BSZ*SEQ)       // 8192
#define NHB    (BSZ*NHEAD)     // 128

#define FMIN_VAL (-3.402823466e38f)

// ---------------------------------------------------------------------------
// Scratch (device globals). k-PERMUTED planes: each 8-float k-group stored
// [k0,k4,k1,k5,k2,k6,k3,k7] so tf32 fragment pairs (k,k+4) load as one LDS.64.
// ---------------------------------------------------------------------------
__device__ float g_Q[MROWS*DMODEL];        // tf32-valued, hd-permuted
__device__ float g_K[MROWS*DMODEL];        // tf32-valued, hd-permuted
__device__ float g_V[MROWS*DMODEL];        // tf32-valued, natural
__device__ float g_A32[MROWS*DMODEL];      // act plane (q) / attn-O, k-permuted
__device__ float g_B32[MROWS*DMODEL];      // act plane (k)
__device__ float g_C32[MROWS*DMODEL];      // act plane (v)
__device__ float g_W32[4*DMODEL*DMODEL];   // weight planes, k-permuted

// ---------------------------------------------------------------------------
// PTX helpers
// ---------------------------------------------------------------------------
#define MMA_TF32(d, a0,a1,a2,a3, b0,b1) \
  asm volatile("mma.sync.aligned.m16n8k8.row.col.f32.tf32.tf32.f32 " \
   "{%0,%1,%2,%3}, {%4,%5,%6,%7}, {%8,%9}, {%0,%1,%2,%3};" \
   : "+f"((d)[0]),"+f"((d)[1]),"+f"((d)[2]),"+f"((d)[3]) \
   : "r"(a0),"r"(a1),"r"(a2),"r"(a3),"r"(b0),"r"(b1))

__device__ __forceinline__ uint32_t rna(float x){
    uint32_t r; asm("cvt.rna.tf32.f32 %0, %1;" : "=r"(r) : "f"(x)); return r;
}
__device__ __forceinline__ uint32_t smem_u32(const void* p){
    uint32_t a;
    asm("{ .reg .u64 t; cvta.to.shared.u64 t, %1; cvt.u32.u64 %0, t; }"
        : "=r"(a) : "l"(p));
    return a;
}
#define CP16(dst,src) asm volatile("cp.async.cg.shared.global [%0], [%1], 16;"::"r"(dst),"l"(src))
#define CP_COMMIT()   asm volatile("cp.async.commit_group;":::"memory")
#define CP_WAIT0()    asm volatile("cp.async.wait_group 0;":::"memory")

// ---------------------------------------------------------------------------
// fp32 -> tf32-rounded, k-group interleaved. One thread per 8-float group.
// ---------------------------------------------------------------------------
__device__ __forceinline__ void conv_group(const float* X, float* Y, int i){
    float4 lo = ((const float4*)X)[2*i];
    float4 hi = ((const float4*)X)[2*i+1];
    uint4 o0, o1;
    o0.x = rna(lo.x); o0.y = rna(hi.x); o0.z = rna(lo.y); o0.w = rna(hi.y);
    o1.x = rna(lo.z); o1.y = rna(hi.z); o1.z = rna(lo.w); o1.w = rna(hi.w);
    ((uint4*)Y)[2*i]   = o0;
    ((uint4*)Y)[2*i+1] = o1;
}

__global__ void __launch_bounds__(256) conv_w4(
    const float* __restrict__ w0, const float* __restrict__ w1,
    const float* __restrict__ w2, const float* __restrict__ w3,
    float* __restrict__ W32, int n8)
{
    int i = blockIdx.x*256 + threadIdx.x;
    if (i >= n8) return;
    const float* src = (blockIdx.y==0) ? w0 : (blockIdx.y==1) ? w1 :
                       (blockIdx.y==2) ? w2 : w3;
    conv_group(src, W32 + (size_t)blockIdx.y*DMODEL*DMODEL, i);
}

__global__ void __launch_bounds__(256) conv_a3(
    const float* __restrict__ x0, const float* __restrict__ x1,
    const float* __restrict__ x2,
    float* __restrict__ y0, float* __restrict__ y1, float* __restrict__ y2,
    int n8)
{
    int i = blockIdx.x*256 + threadIdx.x;
    if (i >= n8) return;
    const float* src = (blockIdx.y==0) ? x0 : (blockIdx.y==1) ? x1 : x2;
    float*       dst = (blockIdx.y==0) ? y0 : (blockIdx.y==1) ? y1 : y2;
    conv_group(src, dst, i);
}

// ---------------------------------------------------------------------------
// GEMM core (R12 champion config): 128x128, 2 CTA/SM, single-stream tf32,
// double-buffered cp.async, LDS.64 fragments on k-permuted planes.
// mode: 0 = plain fp32 out, 1 = rna out (natural), 2 = rna + k-permuted out
// ---------------------------------------------------------------------------
#define GSTR 40
#define GEMM_SMEM (2*2*128*GSTR*4)    // 81920 B

__device__ __forceinline__ void gemm_body(
    const float* __restrict__ A, const float* __restrict__ W,
    const float* __restrict__ bias, float* __restrict__ C,
    float alpha, int mode, float* gsm, uint32_t sbase)
{
    const int tid  = threadIdx.x;
    const int lane = tid & 31;
    const int wid  = tid >> 5;
    const int wm   = (wid & 1) * 64;
    const int wn   = (wid >> 1) * 32;
    const int bm   = blockIdx.y * 128;
    const int bn   = blockIdx.x * 128;

    float acc[4][4][4];
    #pragma unroll
    for (int a=0;a<4;a++)
        #pragma unroll
        for (int b=0;b<4;b++)
            #pragma unroll
            for (int r=0;r<4;r++) acc[a][b][r]=0.f;

    const int lrow = tid >> 3;
    const int lseg = (tid & 7) * 4;

    #define ISSUE_CHUNK(k0, buf)                                               \
    do {                                                                       \
        uint32_t ab = sbase + (buf)*2*128*GSTR*4;                              \
        uint32_t bb = ab + 128*GSTR*4;                                         \
        _Pragma("unroll")                                                      \
        for (int it = 0; it < 4; it++) {                                       \
            int row = it*32 + lrow;                                            \
            CP16(ab + (row*GSTR + lseg)*4,                                     \
                 &A[(size_t)(bm+row)*DMODEL + (k0) + lseg]);                   \
            CP16(bb + (row*GSTR + lseg)*4,                                     \
                 &W[(size_t)(bn+row)*DMODEL + (k0) + lseg]);                   \
        }                                                                      \
        CP_COMMIT();                                                           \
    } while(0)

    ISSUE_CHUNK(0, 0);

    const int q2 = (lane & 3) * 2;
    for (int c = 0; c < 32; c++) {
        CP_WAIT0();
        __syncthreads();   // sole barrier: orders compute(c-1) before issue(c+1)
        if (c < 31) ISSUE_CHUNK((c+1)*32, (c+1)&1);

        const float* As_ = gsm + (c&1)*2*128*GSTR;
        const float* Bs_ = As_ + 128*GSTR;

        #pragma unroll
        for (int ks = 0; ks < 4; ks++) {
            const int kb = ks*8 + q2;
            float2 bfr[4];
            #pragma unroll
            for (int nt = 0; nt < 4; nt++)
                bfr[nt] = *(const float2*)(Bs_ + (wn + nt*8 + (lane>>2))*GSTR + kb);
            #pragma unroll
            for (int mt = 0; mt < 4; mt++) {
                const float* ap = As_ + (wm + mt*16 + (lane>>2))*GSTR + kb;
                float2 aA = *(const float2*)ap;
                float2 aB = *(const float2*)(ap + 8*GSTR);
                uint32_t a0 = __float_as_uint(aA.x);
                uint32_t a2 = __float_as_uint(aA.y);
                uint32_t a1 = __float_as_uint(aB.x);
                uint32_t a3 = __float_as_uint(aB.y);
                #pragma unroll
                for (int nt = 0; nt < 4; nt++)
                    MMA_TF32(acc[mt][nt], a0,a1,a2,a3,
                             __float_as_uint(bfr[nt].x), __float_as_uint(bfr[nt].y));
            }
        }
    }
    #undef ISSUE_CHUNK
    __syncthreads();

    const int q = lane & 3;
    const int pa = (q < 2) ? 4*q     : 4*q - 7;
    const int pb = (q < 2) ? 4*q + 2 : 4*q - 5;
    #pragma unroll
    for (int mt = 0; mt < 4; mt++) {
        const int row = bm + wm + mt*16 + (lane >> 2);
        #pragma unroll
        for (int nt = 0; nt < 4; nt++) {
            const int gb  = bn + wn + nt*8;
            const int col = gb + 2*q;
            const float bx = bias[col], by = bias[col+1];
            float2 v0, v1;
            v0.x = alpha*(acc[mt][nt][0] + bx);
            v0.y = alpha*(acc[mt][nt][1] + by);
            v1.x = alpha*(acc[mt][nt][2] + bx);
            v1.y = alpha*(acc[mt][nt][3] + by);
            if (mode) {
                v0.x = __uint_as_float(rna(v0.x)); v0.y = __uint_as_float(rna(v0.y));
                v1.x = __uint_as_float(rna(v1.x)); v1.y = __uint_as_float(rna(v1.y));
            }
            if (mode == 2) {
                C[(size_t)row*DMODEL + gb + pa]     = v0.x;
                C[(size_t)row*DMODEL + gb + pb]     = v0.y;
                C[(size_t)(row+8)*DMODEL + gb + pa] = v1.x;
                C[(size_t)(row+8)*DMODEL + gb + pb] = v1.y;
            } else {
                *(float2*)&C[(size_t)row*DMODEL + col]     = v0;
                *(float2*)&C[(size_t)(row+8)*DMODEL + col] = v1;
            }
        }
    }
}

__global__ void __launch_bounds__(256,2) gemm_qkv(
    const float* __restrict__ Aq, const float* __restrict__ Ak,
    const float* __restrict__ Av, const float* __restrict__ W32,
    const float* __restrict__ bq, const float* __restrict__ bk,
    const float* __restrict__ bv,
    float* __restrict__ Q, float* __restrict__ K, float* __restrict__ V)
{
    extern __shared__ float gsm[];
    const uint32_t sbase = smem_u32(gsm);
    const int z = blockIdx.z;
    const float* A  = (z==0) ? Aq : (z==1) ? Ak : Av;
    const float* Wz = W32 + (size_t)z*DMODEL*DMODEL;
    const float* bs = (z==0) ? bq : (z==1) ? bk : bv;
    float*       C  = (z==0) ? Q  : (z==1) ? K  : V;
    const float alpha = (z==0) ? 0.25f : 1.0f;
    const int   mode  = (z==2) ? 1 : 2;
    gemm_body(A, Wz, bs, C, alpha, mode, gsm, sbase);
}

__global__ void __launch_bounds__(256,2) gemm_single(
    const float* __restrict__ A, const float* __restrict__ W,
    const float* __restrict__ bias, float* __restrict__ C,
    float alpha, int mode)
{
    extern __shared__ float gsm[];
    gemm_body(A, W, bias, C, alpha, mode, gsm, smem_u32(gsm));
}

// ---------------------------------------------------------------------------
// Flash attention (R12 champion) + LOCAL vsum: the diagonal CTAs (x==7,
// shortest work: 2 tiles) compute their head's V column sums themselves in
// the epilogue, reusing P smem — the standalone vsum kernel is deleted.
// ---------------------------------------------------------------------------
#define ASTR 72
#define A_QS 0
#define A_KS (128*ASTR)
#define A_VS (A_KS + 64*ASTR)
#define A_PS (A_VS + 64*ASTR)
#define ATTN_SMEM ((A_PS + 128*ASTR)*4)   // 110592 B

__global__ void __launch_bounds__(256,2) attn_kernel(
    const float* __restrict__ Qg, const float* __restrict__ Kg,
    const float* __restrict__ Vg, float* __restrict__ O32)
{
    extern __shared__ float smf[];
    const uint32_t sbase = smem_u32(smf);

    const int hb = blockIdx.y;
    const int q0 = blockIdx.x * 128;
    const float* Qh = Qg + (size_t)hb*65536;
    const float* Kh = Kg + (size_t)hb*65536;
    const float* Vh = Vg + (size_t)hb*65536;

    const int tid  = threadIdx.x;
    const int lane = tid & 31;
    const int wid  = tid >> 5;
    const int qr   = (lane >> 2);
    const int qc   = (lane & 3);
    const int q2   = qc * 2;

    const int lrow = tid >> 4;
    const int lseg = (tid & 15) * 4;

    #define ISSUE_KV(kv0)                                                      \
    do {                                                                       \
        _Pragma("unroll")                                                      \
        for (int it = 0; it < 4; it++) {                                       \
            int row = it*16 + lrow;                                            \
            CP16(sbase + (A_KS + row*ASTR + lseg)*4,                           \
                 &Kh[(size_t)((kv0)+row)*HDIM + lseg]);                        \
            CP16(sbase + (A_VS + row*ASTR + lseg)*4,                           \
                 &Vh[(size_t)((kv0)+row)*HDIM + lseg]);                        \
        }                                                                      \
        CP_COMMIT();                                                           \
    } while(0)

    const int t0 = 2*blockIdx.x;

    #pragma unroll
    for (int it = 0; it < 8; it++) {
        int row = it*16 + lrow;
        CP16(sbase + (A_QS + row*ASTR + lseg)*4,
             &Qh[(size_t)(q0+row)*HDIM + lseg]);
    }
    ISSUE_KV(t0*64);

    float oa[8][4];
    #pragma unroll
    for (int nt=0;nt<8;nt++)
        #pragma unroll
        for (int r=0;r<4;r++) oa[nt][r]=0.f;
    float l0 = 0.f, l1 = 0.f;

    const int rloc = wid*16 + qr;
    const int rg0  = q0 + rloc;
    const int rg1  = rg0 + 8;
    const float* Qs = smf + A_QS;
    const float* Ks = smf + A_KS;
    const float* Vs = smf + A_VS;
    float*       Ps = smf + A_PS;

    const int pa = (qc < 2) ? 4*qc     : 4*qc - 7;
    const int pb = (qc < 2) ? 4*qc + 2 : 4*qc - 5;

    for (int t = t0; t < 16; t++) {
        const int kv0 = t*64;
        CP_WAIT0();
        __syncthreads();

        // ---- S = Q @ K^T ----
        float sa[8][4];
        #pragma unroll
        for (int nt=0;nt<8;nt++)
            #pragma unroll
            for (int r=0;r<4;r++) sa[nt][r]=0.f;

        #pragma unroll
        for (int ks = 0; ks < 8; ks++) {
            const int kb = ks*8 + q2;
            float2 qA = *(const float2*)(Qs + rloc*ASTR + kb);
            float2 qB = *(const float2*)(Qs + (rloc+8)*ASTR + kb);
            uint32_t a0 = __float_as_uint(qA.x);
            uint32_t a2 = __float_as_uint(qA.y);
            uint32_t a1 = __float_as_uint(qB.x);
            uint32_t a3 = __float_as_uint(qB.y);
            #pragma unroll
            for (int nt = 0; nt < 8; nt++) {
                float2 kf = *(const float2*)(Ks + (qr + nt*8)*ASTR + kb);
                MMA_TF32(sa[nt], a0,a1,a2,a3,
                         __float_as_uint(kf.x), __float_as_uint(kf.y));
            }
        }

        // ---- mask + exp + row sums ----
        float ts0 = 0.f, ts1 = 0.f;
        #pragma unroll
        for (int nt = 0; nt < 8; nt++) {
            const int cg = kv0 + nt*8 + q2;
            if (cg   <= rg0) sa[nt][0] = FMIN_VAL;
            if (cg+1 <= rg0) sa[nt][1] = FMIN_VAL;
            if (cg   <= rg1) sa[nt][2] = FMIN_VAL;
            if (cg+1 <= rg1) sa[nt][3] = FMIN_VAL;
            sa[nt][0] = __expf(sa[nt][0]);
            sa[nt][1] = __expf(sa[nt][1]);
            sa[nt][2] = __expf(sa[nt][2]);
            sa[nt][3] = __expf(sa[nt][3]);
            ts0 += sa[nt][0] + sa[nt][1];
            ts1 += sa[nt][2] + sa[nt][3];
        }
        ts0 += __shfl_xor_sync(0xffffffffu, ts0, 1);
        ts0 += __shfl_xor_sync(0xffffffffu, ts0, 2);
        ts1 += __shfl_xor_sync(0xffffffffu, ts1, 1);
        ts1 += __shfl_xor_sync(0xffffffffu, ts1, 2);
        l0 += ts0;
        l1 += ts1;

        // ---- P (tf32 bits) -> smem, key-permuted, warp-private rows ----
        #pragma unroll
        for (int nt = 0; nt < 8; nt++) {
            float* pr0 = Ps + rloc*ASTR + nt*8;
            float* pr1 = Ps + (rloc+8)*ASTR + nt*8;
            pr0[pa] = __uint_as_float(rna(sa[nt][0]));
            pr0[pb] = __uint_as_float(rna(sa[nt][1]));
            pr1[pa] = __uint_as_float(rna(sa[nt][2]));
            pr1[pb] = __uint_as_float(rna(sa[nt][3]));
        }
        __syncwarp();

        // ---- O += P @ V ----
        #pragma unroll
        for (int ks = 0; ks < 8; ks++) {
            const int kb = ks*8 + q2;
            float2 pA = *(const float2*)(Ps + rloc*ASTR + kb);
            float2 pB = *(const float2*)(Ps + (rloc+8)*ASTR + kb);
            uint32_t a0 = __float_as_uint(pA.x);
            uint32_t a2 = __float_as_uint(pA.y);
            uint32_t a1 = __float_as_uint(pB.x);
            uint32_t a3 = __float_as_uint(pB.y);
            const float* vb = Vs + (ks*8 + qc)*ASTR + qr;
            #pragma unroll
            for (int nt = 0; nt < 8; nt++) {
                uint32_t b0 = __float_as_uint(vb[nt*8]);
                uint32_t b1 = __float_as_uint(vb[4*ASTR + nt*8]);
                MMA_TF32(oa[nt], a0,a1,a2,a3, b0,b1);
            }
        }
        __syncthreads();
        if (t < 15) ISSUE_KV(kv0+64);
    }
    #undef ISSUE_KV

    // ---- fully-masked row (qg = SEQ-1): uniform softmax = mean(V) ----
    // Only the diagonal CTA (blockIdx.x == 7) contains that row; it computes
    // its head's V column sums locally (P smem is dead now).
    if (blockIdx.x == 7) {
        float* red = Ps;                       // [4][64] scratch
        const int c = tid & 63;
        const int g = tid >> 6;                // 0..3, 256 rows each
        const float* p = Vh + (size_t)(g*256)*HDIM + c;
        float s0=0.f, s1=0.f, s2=0.f, s3=0.f;
        #pragma unroll 8
        for (int r = 0; r < 256; r += 4) {
            s0 += p[(r+0)*HDIM];
            s1 += p[(r+1)*HDIM];
            s2 += p[(r+2)*HDIM];
            s3 += p[(r+3)*HDIM];
        }
        red[g*64 + c] = (s0+s1) + (s2+s3);
        __syncthreads();
        if (rg1 == SEQ-1) {
            l1 = (float)SEQ;
            #pragma unroll
            for (int nt = 0; nt < 8; nt++) {
                const int col = nt*8 + q2;
                oa[nt][2] = (red[col]   + red[64+col])   + (red[128+col]   + red[192+col]);
                oa[nt][3] = (red[col+1] + red[64+col+1]) + (red[128+col+1] + red[192+col+1]);
            }
        }
    }

    // ---- normalize + rna + k-permuted store at the FLAT O position ----
    const float i0 = 1.f / l0, i1 = 1.f / l1;
    const size_t slab = (size_t)hb * 65536;
    #pragma unroll
    for (int nt = 0; nt < 8; nt++) {
        float* o0 = O32 + slab + (size_t)rg0*HDIM + nt*8;
        float* o1 = O32 + slab + (size_t)rg1*HDIM + nt*8;
        o0[pa] = __uint_as_float(rna(oa[nt][0]*i0));
        o0[pb] = __uint_as_float(rna(oa[nt][1]*i0));
        o1[pa] = __uint_as_float(rna(oa[nt][2]*i1));
        o1[pb] = __uint_as_float(rna(oa[nt][3]*i1));
    }
}

// ---------------------------------------------------------------------------
// Launch
// ---------------------------------------------------------------------------
extern "C" void kernel_launch(void* const* d_in, const int* in_sizes, int n_in,
                              void* d_out, int out_size) {
    const float* q_in = (const float*)d_in[0];
    const float* k_in = (const float*)d_in[1];
    const float* v_in = (const float*)d_in[2];
    const float* wq   = (const float*)d_in[3];
    const float* bq   = (const float*)d_in[4];
    const float* wk   = (const float*)d_in[5];
    const float* bk   = (const float*)d_in[6];
    const float* wv   = (const float*)d_in[7];
    const float* bv   = (const float*)d_in[8];
    const float* wo   = (const float*)d_in[9];
    const float* bo   = (const float*)d_in[10];
    float* out = (float*)d_out;

    float *Qp, *Kp, *Vp, *A32, *B32, *C32, *W32;
    cudaGetSymbolAddress((void**)&Qp,  g_Q);
    cudaGetSymbolAddress((void**)&Kp,  g_K);
    cudaGetSymbolAddress((void**)&Vp,  g_V);
    cudaGetSymbolAddress((void**)&A32, g_A32);
    cudaGetSymbolAddress((void**)&B32, g_B32);
    cudaGetSymbolAddress((void**)&C32, g_C32);
    cudaGetSymbolAddress((void**)&W32, g_W32);

    cudaFuncSetAttribute(gemm_qkv,    cudaFuncAttributeMaxDynamicSharedMemorySize, GEMM_SMEM);
    cudaFuncSetAttribute(gemm_single, cudaFuncAttributeMaxDynamicSharedMemorySize, GEMM_SMEM);
    cudaFuncSetAttribute(attn_kernel, cudaFuncAttributeMaxDynamicSharedMemorySize, ATTN_SMEM);

    const int WP = DMODEL*DMODEL;
    dim3 blk(256);
    const int NA8 = MROWS*DMODEL/8;
    const int NW8 = DMODEL*DMODEL/8;

    // tf32 plane conversions
    conv_w4<<<dim3(NW8/256, 4), blk>>>(wq, wk, wv, wo, W32, NW8);
    conv_a3<<<dim3(NA8/256, 3), blk>>>(q_in, k_in, v_in, A32, B32, C32, NA8);

    // Fused Q/K/V projections (128x128 tiles, wave-packed)
    dim3 gqkv(DMODEL/128, MROWS/128, 3);  // (8, 64, 3)
    gemm_qkv<<<gqkv, blk, GEMM_SMEM>>>(A32, B32, C32, W32, bq, bk, bv, Qp, Kp, Vp);

    // Attention (tile skipping, no online max, local vsum in diagonal CTAs)
    dim3 gattn(SEQ/128, NHB);            // (8, 128)
    attn_kernel<<<gattn, blk, ATTN_SMEM>>>(Qp, Kp, Vp, A32);

    // Output projection
    dim3 gproj(DMODEL/128, MROWS/128);   // (8, 64)
    gemm_single<<<gproj, blk, GEMM_SMEM>>>(A32, W32+3*WP, bo, out, 1.0f, 0);
}